// round 2
// baseline (speedup 1.0000x reference)
#include <cuda_runtime.h>
#include <cuda_bf16.h>
#include <cstdint>

// ---------------------------------------------------------------------------
// Problem constants
// ---------------------------------------------------------------------------
#define THREADS 256
#define F_DIM 160
#define NQ 4096
#define NA 32768
#define NC 10
#define SPLITS 32
#define A_CHUNK 1024          // addresses per CTA
#define NTILES 8              // 128-wide N tiles per CTA
#define KEXP (-1.31154095f)   // -log2(e)/1.1 : exp(-d/1.1) = 2^(d*KEXP)

// ---------------------------------------------------------------------------
// Shared memory layout (byte offsets; all row strides multiple of 16B and
// chosen so ldmatrix 8-row groups hit distinct bank quads -> conflict-free)
// ---------------------------------------------------------------------------
#define XROWB 656                     // 164 floats (160 used): 164%32=4
#define YROWB 336                     // 84 floats  (80 used):  84%32=20
#define WROWB 272                     // 136 bf16   (128 used): 68%32=4
#define OFF_X   0
#define SZ_X    (128 * XROWB)         // 83968
#define OFF_Y0  SZ_X
#define SZ_YBUF (128 * YROWB)         // 43008
#define OFF_Y1  (OFF_Y0 + SZ_YBUF)
#define OFF_W   (OFF_Y1 + SZ_YBUF)    // 169984
#define SZ_W    (128 * WROWB)         // 34816
#define OFF_MT  (OFF_W + SZ_W)        // 204800  Mt[16][136] bf16 (M^T + ones)
#define SZ_MT   (16 * WROWB)          // 4352
#define OFF_Y2S (OFF_MT + SZ_MT)      // 209152  y2 chunk [128] f32
#define OFF_X2S (OFF_Y2S + 512)       // 209664  x2 tile  [128] f32
#define SMEM_BYTES (OFF_X2S + 512)    // 210176

// ---------------------------------------------------------------------------
// Device scratch (no cudaMalloc allowed)
// ---------------------------------------------------------------------------
__device__ float g_x2[NQ];
__device__ float g_y2[NA];
__device__ float g_part[(size_t)SPLITS * NQ * 16];  // [split][row][16]: 10 num, den@10

// ---------------------------------------------------------------------------
// PTX helpers (sm_80-compatible subset only: ldmatrix / mma.sync / cp.async)
// ---------------------------------------------------------------------------
__device__ __forceinline__ uint32_t cvta_s(const void* p) {
    uint32_t r;
    asm("{ .reg .u64 t; cvta.to.shared.u64 t, %1; cvt.u32.u64 %0, t; }"
        : "=r"(r) : "l"(p));
    return r;
}

#define LDMX4(r, a)                                                            \
    asm volatile("ldmatrix.sync.aligned.m8n8.x4.shared.b16 {%0,%1,%2,%3}, [%4];" \
                 : "=r"((r)[0]), "=r"((r)[1]), "=r"((r)[2]), "=r"((r)[3])      \
                 : "r"(a))

#define MMA_TF32(d, a, b0, b1)                                                 \
    asm volatile("mma.sync.aligned.m16n8k8.row.col.f32.tf32.tf32.f32 "         \
                 "{%0,%1,%2,%3},{%4,%5,%6,%7},{%8,%9},{%0,%1,%2,%3};"          \
                 : "+f"((d)[0]), "+f"((d)[1]), "+f"((d)[2]), "+f"((d)[3])      \
                 : "r"((a)[0]), "r"((a)[1]), "r"((a)[2]), "r"((a)[3]),         \
                   "r"(b0), "r"(b1))

#define MMA_BF16(d, a, b0, b1)                                                 \
    asm volatile("mma.sync.aligned.m16n8k16.row.col.f32.bf16.bf16.f32 "        \
                 "{%0,%1,%2,%3},{%4,%5,%6,%7},{%8,%9},{%0,%1,%2,%3};"          \
                 : "+f"((d)[0]), "+f"((d)[1]), "+f"((d)[2]), "+f"((d)[3])      \
                 : "r"((a)[0]), "r"((a)[1]), "r"((a)[2]), "r"((a)[3]),         \
                   "r"(b0), "r"(b1))

#define CPASYNC16(d, s)                                                        \
    asm volatile("cp.async.cg.shared.global [%0], [%1], 16;" :: "r"(d), "l"(s))
#define CPCOMMIT() asm volatile("cp.async.commit_group;" ::: "memory")
#define CPWAIT1()  asm volatile("cp.async.wait_group 1;" ::: "memory")

// issue cp.async for one Y K-half tile: rows [a0row, a0row+128), floats [h*80, h*80+80)
__device__ __forceinline__ void issue_y_half(const float* __restrict__ Y,
                                             int a0row, int h, uint32_t dbase,
                                             int tid) {
    const char* gs = (const char*)(Y + (size_t)a0row * F_DIM + h * 80);
    #pragma unroll
    for (int k = 0; k < 10; k++) {
        int i = k * THREADS + tid;        // 0..2559 over 128 rows x 20 float4
        int r = i / 20, c = i - r * 20;
        CPASYNC16(dbase + r * YROWB + c * 16, gs + (size_t)r * 640 + c * 16);
    }
}

// ---------------------------------------------------------------------------
// Kernel 0: exact fp32 row norms for X and Y
// ---------------------------------------------------------------------------
__global__ void norms_kernel(const float* __restrict__ X, const float* __restrict__ Y) {
    int gw = (int)((blockIdx.x * blockDim.x + threadIdx.x) >> 5);
    int lane = threadIdx.x & 31;
    const float* src;
    float* dst;
    if (gw < NQ)            { src = X + (size_t)gw * F_DIM;        dst = g_x2 + gw; }
    else if (gw < NQ + NA)  { src = Y + (size_t)(gw - NQ) * F_DIM; dst = g_y2 + (gw - NQ); }
    else return;
    float s = 0.f;
    #pragma unroll
    for (int k = lane; k < F_DIM; k += 32) { float v = src[k]; s = fmaf(v, v, s); }
    #pragma unroll
    for (int o = 16; o > 0; o >>= 1) s += __shfl_xor_sync(0xFFFFFFFFu, s, o);
    if (lane == 0) *dst = s;
}

// ---------------------------------------------------------------------------
// Kernel 1: fused  scores(tf32 mma) -> softmin weights -> (W @ [M|1]) (bf16 mma)
// grid = 32 m-tiles x 32 A-splits; 256 threads (8 warps), 1 CTA/SM
// warp grid for GEMM-1: 4(m) x 2(n); warp tile 32x64
// ---------------------------------------------------------------------------
__global__ void __launch_bounds__(THREADS, 1) fused_kernel(
    const float* __restrict__ X, const float* __restrict__ Y,
    const float* __restrict__ Mv)
{
    extern __shared__ __align__(1024) char sm[];
    const uint32_t sb = cvta_s(sm);
    const int tid  = threadIdx.x;
    const int lane = tid & 31, warp = tid >> 5;
    const int mw = warp >> 1, nw = warp & 1;
    const int g = lane >> 2, tig = lane & 3;
    const int m_tile = (int)blockIdx.x >> 5;
    const int split  = (int)blockIdx.x & (SPLITS - 1);
    const int a_start = split * A_CHUNK;

    // --- prologue: async-load Y tile 0 (both K-halves) ------------------
    issue_y_half(Y, a_start, 0, sb + OFF_Y0, tid); CPCOMMIT();
    issue_y_half(Y, a_start, 1, sb + OFF_Y1, tid); CPCOMMIT();

    // --- X tile (once per CTA), x2 chunk, constant Mt rows --------------
    {
        const float4* Xg = (const float4*)(X + (size_t)m_tile * 128 * F_DIM);
        #pragma unroll
        for (int k = 0; k < 20; k++) {
            int i = k * THREADS + tid;    // 128 rows x 40 float4
            int r = i / 40, c = i - r * 40;
            float4 v = Xg[(size_t)r * 40 + c];
            *(float4*)(sm + OFF_X + r * XROWB + c * 16) = v;
        }
    }
    if (tid < 128) ((float*)(sm + OFF_X2S))[tid] = g_x2[m_tile * 128 + tid];
    {   // Mt rows 10..15: ones column (den) then zero pad
        __nv_bfloat16 one = __float2bfloat16(1.0f);
        __nv_bfloat16 zro = __float2bfloat16(0.0f);
        for (int i = tid; i < 6 * 128; i += THREADS) {
            int c = 10 + i / 128, j = i - (c - 10) * 128;
            *(__nv_bfloat16*)(sm + OFF_MT + c * WROWB + j * 2) = (c == 10) ? one : zro;
        }
    }
    __syncthreads();

    // --- per-thread ldmatrix bases --------------------------------------
    uint32_t aA[2];
    #pragma unroll
    for (int mf = 0; mf < 2; mf++)
        aA[mf] = sb + OFF_X +
                 (mw * 32 + mf * 16 + (lane & 7) + (lane & 8)) * XROWB +
                 ((lane >> 4) & 1) * 16;
    uint32_t bBo[4];
    #pragma unroll
    for (int p = 0; p < 4; p++)
        bBo[p] = (uint32_t)((nw * 64 + p * 16 + ((lane >> 4) & 1) * 8 + (lane & 7)) * YROWB +
                            ((lane >> 3) & 1) * 16);
    const uint32_t aWb = sb + OFF_W +
                         (warp * 16 + (lane & 7) + (lane & 8)) * WROWB +
                         ((lane >> 4) & 1) * 16;
    const uint32_t bMb = sb + OFF_MT +
                         ((lane & 7) + ((lane >> 4) & 1) * 8) * WROWB +
                         ((lane >> 3) & 1) * 16;

    float x2a[4];   // rows mw*32 + (q>>1)*16 + (q&1)*8 + g
    {
        const float* x2s = (const float*)(sm + OFF_X2S);
        #pragma unroll
        for (int q = 0; q < 4; q++)
            x2a[q] = x2s[mw * 32 + (q >> 1) * 16 + (q & 1) * 8 + g];
    }

    float acc2[2][4] = {{0.f, 0.f, 0.f, 0.f}, {0.f, 0.f, 0.f, 0.f}};
    float acc[2][8][4];

    for (int t = 0; t < NTILES; t++) {
        float mv[5];
        float y2v = 0.f;
        #pragma unroll
        for (int h = 0; h < 2; h++) {
            if (h == 0) {
                // prefetch next M tile + y2 chunk into registers (hidden by mma)
                #pragma unroll
                for (int k = 0; k < 5; k++) {
                    int i = k * THREADS + tid;          // < 1280 = 128*10
                    int j = i / 10, c = i - j * 10;
                    mv[k] = Mv[(size_t)(a_start + t * 128 + j) * NC + c];
                }
                if (tid < 128) y2v = g_y2[a_start + t * 128 + tid];
                #pragma unroll
                for (int mf = 0; mf < 2; mf++)
                    #pragma unroll
                    for (int nf = 0; nf < 8; nf++)
                        #pragma unroll
                        for (int q = 0; q < 4; q++) acc[mf][nf][q] = 0.f;
            }
            CPWAIT1();              // K-half buffer [h] for tile t is ready
            __syncthreads();

            // ---- 10 tf32 K-steps on this K-half -------------------------
            {
                const uint32_t yB = sb + OFF_Y0 + h * SZ_YBUF;
                #pragma unroll
                for (int ks = 0; ks < 10; ks++) {
                    uint32_t afr[2][4], bfr[4][4];
                    #pragma unroll
                    for (int mf = 0; mf < 2; mf++)
                        LDMX4(afr[mf], aA[mf] + (h * 10 + ks) * 32);
                    #pragma unroll
                    for (int p = 0; p < 4; p++)
                        LDMX4(bfr[p], yB + bBo[p] + ks * 32);
                    #pragma unroll
                    for (int mf = 0; mf < 2; mf++)
                        #pragma unroll
                        for (int nf = 0; nf < 8; nf++) {
                            int p = nf >> 1, o = nf & 1;
                            MMA_TF32(acc[mf][nf], afr[mf], bfr[p][o * 2], bfr[p][o * 2 + 1]);
                        }
                }
            }
            if (h == 0) {   // publish Mt (transposed, bf16) + y2 chunk
                #pragma unroll
                for (int k = 0; k < 5; k++) {
                    int i = k * THREADS + tid;
                    int j = i / 10, c = i - j * 10;
                    *(__nv_bfloat16*)(sm + OFF_MT + c * WROWB + j * 2) = __float2bfloat16(mv[k]);
                }
                if (tid < 128) ((float*)(sm + OFF_Y2S))[tid] = y2v;
            }
            __syncthreads();        // all warps done reading buffer [h]
            if (t + 1 < NTILES)
                issue_y_half(Y, a_start + (t + 1) * 128, h,
                             sb + OFF_Y0 + h * SZ_YBUF, tid);
            CPCOMMIT();             // always commit (possibly empty) for uniform accounting

            if (h == 1) {
                // ---- epilogue: d2 -> sqrt -> exp -> bf16 W tile ----------
                {
                    const float* y2s = (const float*)(sm + OFF_Y2S);
                    float y2l[16];
                    #pragma unroll
                    for (int nf = 0; nf < 8; nf++) {
                        y2l[nf * 2]     = y2s[nw * 64 + nf * 8 + tig * 2];
                        y2l[nf * 2 + 1] = y2s[nw * 64 + nf * 8 + tig * 2 + 1];
                    }
                    #pragma unroll
                    for (int mf = 0; mf < 2; mf++) {
                        #pragma unroll
                        for (int nf = 0; nf < 8; nf++) {
                            float w[4];
                            #pragma unroll
                            for (int q = 0; q < 4; q++) {
                                float d2 = fmaf(-2.f, acc[mf][nf][q],
                                                x2a[mf * 2 + (q >> 1)] + y2l[nf * 2 + (q & 1)]);
                                d2 = fmaxf(d2, 0.f);
                                float d;
                                asm("sqrt.approx.ftz.f32 %0, %1;" : "=f"(d) : "f"(d2));
                                asm("ex2.approx.ftz.f32 %0, %1;" : "=f"(w[q]) : "f"(d * KEXP));
                            }
                            __nv_bfloat162 p0 = __floats2bfloat162_rn(w[0], w[1]);
                            __nv_bfloat162 p1 = __floats2bfloat162_rn(w[2], w[3]);
                            int colb = (nw * 64 + nf * 8 + tig * 2) * 2;
                            int r0 = mw * 32 + mf * 16 + g;
                            *(__nv_bfloat162*)(sm + OFF_W + r0 * WROWB + colb) = p0;
                            *(__nv_bfloat162*)(sm + OFF_W + (r0 + 8) * WROWB + colb) = p1;
                        }
                    }
                }
                __syncthreads();    // W tile complete
                // ---- GEMM-2: acc2 += W[128x128] @ Mt^T[128x16] -----------
                #pragma unroll
                for (int k2 = 0; k2 < 8; k2++) {
                    uint32_t aw[4], bm[4];
                    LDMX4(aw, aWb + k2 * 32);
                    LDMX4(bm, bMb + k2 * 32);
                    MMA_BF16(acc2[0], aw, bm[0], bm[1]);
                    MMA_BF16(acc2[1], aw, bm[2], bm[3]);
                }
                // next tile's first __syncthreads protects W/Mt reuse
            }
        }
    }

    // --- write per-split partials: rows warp*16+g(+8), cols nf*8+2tig(+1)
    {
        int r0 = m_tile * 128 + warp * 16 + g;
        size_t base = ((size_t)split * NQ + r0) * 16 + tig * 2;
        #pragma unroll
        for (int nf = 0; nf < 2; nf++) {
            *(float2*)&g_part[base + nf * 8]          = make_float2(acc2[nf][0], acc2[nf][1]);
            *(float2*)&g_part[base + 8 * 16 + nf * 8] = make_float2(acc2[nf][2], acc2[nf][3]);
        }
    }
}

// ---------------------------------------------------------------------------
// Kernel 2: combine splits, normalize
// block = 256 threads = 16 rows x 16 cols; grid = 4096/16 = 256
// ---------------------------------------------------------------------------
__global__ void combine_kernel(float* __restrict__ out) {
    __shared__ float dsh[16];
    int tid = threadIdx.x;
    int il = tid >> 4, c = tid & 15;
    int i = blockIdx.x * 16 + il;
    float s = 0.f;
    #pragma unroll 4
    for (int sp = 0; sp < SPLITS; sp++)
        s += g_part[((size_t)sp * NQ + i) * 16 + c];
    if (c == 10) dsh[il] = s;
    __syncthreads();
    if (c < 10) out[(size_t)i * NC + c] = s / dsh[il];
}

// ---------------------------------------------------------------------------
// kernel_launch
// ---------------------------------------------------------------------------
extern "C" void kernel_launch(void* const* d_in, const int* in_sizes, int n_in,
                              void* d_out, int out_size) {
    const float* X  = (const float*)d_in[0];   // inputs  [4096, 160]
    const float* Y  = (const float*)d_in[1];   // Address [32768, 160]
    const float* Mv = (const float*)d_in[2];   // M       [32768, 10]
    float* out = (float*)d_out;                // [4096, 10]

    static bool attr_done = false;
    if (!attr_done) {
        cudaFuncSetAttribute(fused_kernel,
                             cudaFuncAttributeMaxDynamicSharedMemorySize, SMEM_BYTES);
        attr_done = true;
    }

    int norm_warps = NQ + NA;
    norms_kernel<<<(norm_warps * 32 + 255) / 256, 256>>>(X, Y);
    fused_kernel<<<(NQ / 128) * SPLITS, THREADS, SMEM_BYTES>>>(X, Y, Mv);
    combine_kernel<<<NQ / 16, 256>>>(out);
}

// round 3
// speedup vs baseline: 1.4176x; 1.4176x over previous
#include <cuda_runtime.h>
#include <cuda_fp16.h>
#include <cuda_bf16.h>
#include <cstdint>

// ---------------------------------------------------------------------------
// Problem constants
// ---------------------------------------------------------------------------
#define THREADS 256
#define F_DIM 160
#define NQ 4096
#define NA 32768
#define NC 10
#define SPLITS 32
#define A_CHUNK 1024          // addresses per CTA
#define NTILES 8              // 128-wide N tiles per CTA
#define KEXP (-1.31154095f)   // -log2(e)/1.1 : exp(-d/1.1) = 2^(d*KEXP)

// ---------------------------------------------------------------------------
// Shared memory layout. fp16 tiles: 128 rows x 160 halves (320B) padded to
// 336B rows -> 8-row ldmatrix groups hit 8 distinct bank quads (336/4=84,
// 84*r mod 32 = {0,20,8,28,16,4,24,12}) -> conflict-free.
// ---------------------------------------------------------------------------
#define ROWB 336
#define WROWB 272                      // 136 bf16; 68*r mod 32 distinct quads
#define OFF_X   0
#define SZ_X    (128 * ROWB)           // 43008
#define OFF_Y0  SZ_X                   // 43008
#define SZ_YBUF (128 * ROWB)           // 43008
#define OFF_Y1  (OFF_Y0 + SZ_YBUF)     // 86016
#define OFF_W   (OFF_Y1 + SZ_YBUF)     // 129024
#define SZ_W    (128 * WROWB)          // 34816
#define OFF_MT  (OFF_W + SZ_W)         // 163840  Mt[16][136] bf16 (M^T + ones)
#define SZ_MT   (16 * WROWB)           // 4352
#define OFF_Y2S (OFF_MT + SZ_MT)       // 168192  y2 chunk [128] f32
#define OFF_X2S (OFF_Y2S + 512)        // 168704  x2 tile  [128] f32
#define SMEM_BYTES (OFF_X2S + 512)     // 169216

// ---------------------------------------------------------------------------
// Device scratch (no cudaMalloc allowed)
// ---------------------------------------------------------------------------
__device__ __half g_xh[(size_t)NQ * F_DIM];
__device__ __half g_yh[(size_t)NA * F_DIM];
__device__ float g_x2[NQ];
__device__ float g_y2[NA];
__device__ float g_part[(size_t)SPLITS * NQ * 16];  // [split][row][16]: 10 num, den@10

// ---------------------------------------------------------------------------
// PTX helpers (sm_80-compatible subset: ldmatrix / mma.sync / cp.async)
// ---------------------------------------------------------------------------
__device__ __forceinline__ uint32_t cvta_s(const void* p) {
    uint32_t r;
    asm("{ .reg .u64 t; cvta.to.shared.u64 t, %1; cvt.u32.u64 %0, t; }"
        : "=r"(r) : "l"(p));
    return r;
}

#define LDMX4(r, a)                                                            \
    asm volatile("ldmatrix.sync.aligned.m8n8.x4.shared.b16 {%0,%1,%2,%3}, [%4];" \
                 : "=r"((r)[0]), "=r"((r)[1]), "=r"((r)[2]), "=r"((r)[3])      \
                 : "r"(a))

#define MMA_F16(d, a, b0, b1)                                                  \
    asm volatile("mma.sync.aligned.m16n8k16.row.col.f32.f16.f16.f32 "          \
                 "{%0,%1,%2,%3},{%4,%5,%6,%7},{%8,%9},{%0,%1,%2,%3};"          \
                 : "+f"((d)[0]), "+f"((d)[1]), "+f"((d)[2]), "+f"((d)[3])      \
                 : "r"((a)[0]), "r"((a)[1]), "r"((a)[2]), "r"((a)[3]),         \
                   "r"(b0), "r"(b1))

#define MMA_BF16(d, a, b0, b1)                                                 \
    asm volatile("mma.sync.aligned.m16n8k16.row.col.f32.bf16.bf16.f32 "        \
                 "{%0,%1,%2,%3},{%4,%5,%6,%7},{%8,%9},{%0,%1,%2,%3};"          \
                 : "+f"((d)[0]), "+f"((d)[1]), "+f"((d)[2]), "+f"((d)[3])      \
                 : "r"((a)[0]), "r"((a)[1]), "r"((a)[2]), "r"((a)[3]),         \
                   "r"(b0), "r"(b1))

#define CPASYNC16(d, s)                                                        \
    asm volatile("cp.async.cg.shared.global [%0], [%1], 16;" :: "r"(d), "l"(s))
#define CPCOMMIT() asm volatile("cp.async.commit_group;" ::: "memory")
#define CPWAIT1()  asm volatile("cp.async.wait_group 1;" ::: "memory")

// issue cp.async for one Y tile (fp16): rows [a0row, a0row+128), 320B/row
__device__ __forceinline__ void issue_y(int a0row, uint32_t dbase, int tid) {
    const char* gs = (const char*)(g_yh + (size_t)a0row * F_DIM);
    #pragma unroll
    for (int k = 0; k < 10; k++) {
        int i = k * THREADS + tid;        // 128 rows x 20 x 16B
        int r = i / 20, c = i - r * 20;
        CPASYNC16(dbase + r * ROWB + c * 16, gs + (size_t)r * 320 + c * 16);
    }
}

// ---------------------------------------------------------------------------
// Kernel 0: exact fp32 row norms + fp16 conversion for X and Y
// ---------------------------------------------------------------------------
__global__ void norms_kernel(const float* __restrict__ X, const float* __restrict__ Y) {
    int gw = (int)((blockIdx.x * blockDim.x + threadIdx.x) >> 5);
    int lane = threadIdx.x & 31;
    const float* src;
    __half* dsth;
    float* dst;
    if (gw < NQ) {
        src = X + (size_t)gw * F_DIM; dsth = g_xh + (size_t)gw * F_DIM; dst = g_x2 + gw;
    } else if (gw < NQ + NA) {
        int r = gw - NQ;
        src = Y + (size_t)r * F_DIM; dsth = g_yh + (size_t)r * F_DIM; dst = g_y2 + r;
    } else return;
    float s = 0.f;
    #pragma unroll
    for (int k = lane; k < F_DIM; k += 32) {
        float v = src[k];
        s = fmaf(v, v, s);
        dsth[k] = __float2half_rn(v);
    }
    #pragma unroll
    for (int o = 16; o > 0; o >>= 1) s += __shfl_xor_sync(0xFFFFFFFFu, s, o);
    if (lane == 0) *dst = s;
}

// ---------------------------------------------------------------------------
// Kernel 1: fused  scores(fp16 mma) -> softmin weights -> (W @ [M|1]) (bf16 mma)
// grid = 32 m-tiles x 32 A-splits; 256 threads (8 warps), 1 CTA/SM
// GEMM-1 warp grid 4(m) x 2(n); warp tile 32x64
// ---------------------------------------------------------------------------
__global__ void __launch_bounds__(THREADS, 1) fused_kernel(
    const float* __restrict__ Mv)
{
    extern __shared__ __align__(1024) char sm[];
    const uint32_t sb = cvta_s(sm);
    const int tid  = threadIdx.x;
    const int lane = tid & 31, warp = tid >> 5;
    const int mw = warp >> 1, nw = warp & 1;
    const int g = lane >> 2, tig = lane & 3;
    const int m_tile = (int)blockIdx.x >> 5;
    const int split  = (int)blockIdx.x & (SPLITS - 1);
    const int a_start = split * A_CHUNK;

    // --- prologue: async-load Y tiles 0 and 1 ---------------------------
    issue_y(a_start, sb + OFF_Y0, tid); CPCOMMIT();
    issue_y(a_start + 128, sb + OFF_Y1, tid); CPCOMMIT();

    // --- X tile (fp16, once per CTA), x2 chunk, constant Mt rows --------
    {
        const char* xg = (const char*)(g_xh + (size_t)m_tile * 128 * F_DIM);
        #pragma unroll
        for (int k = 0; k < 10; k++) {
            int i = k * THREADS + tid;
            int r = i / 20, c = i - r * 20;
            *(uint4*)(sm + OFF_X + r * ROWB + c * 16) =
                *(const uint4*)(xg + (size_t)r * 320 + c * 16);
        }
    }
    if (tid < 128) ((float*)(sm + OFF_X2S))[tid] = g_x2[m_tile * 128 + tid];
    {   // Mt rows 10..15: ones column (den) then zero pad
        __nv_bfloat16 one = __float2bfloat16(1.0f);
        __nv_bfloat16 zro = __float2bfloat16(0.0f);
        for (int i = tid; i < 6 * 128; i += THREADS) {
            int c = 10 + i / 128, j = i - (c - 10) * 128;
            *(__nv_bfloat16*)(sm + OFF_MT + c * WROWB + j * 2) = (c == 10) ? one : zro;
        }
    }
    __syncthreads();

    // --- per-thread ldmatrix bases (fp16 16x16 tiles) -------------------
    const int lrow = (lane & 7) + ((lane >> 3) & 1) * 8;
    const int lcol = ((lane >> 4) & 1) * 16;      // byte offset (k 0-7 | 8-15)
    uint32_t aA[2];
    #pragma unroll
    for (int mf = 0; mf < 2; mf++)
        aA[mf] = sb + OFF_X + (mw * 32 + mf * 16 + lrow) * ROWB + lcol;
    uint32_t bBo[4];
    #pragma unroll
    for (int p = 0; p < 4; p++)
        bBo[p] = (uint32_t)((nw * 64 + p * 16 + lrow) * ROWB + lcol);
    const uint32_t aWb = sb + OFF_W + (warp * 16 + lrow) * WROWB + lcol;
    const uint32_t bMb = sb + OFF_MT + lrow * WROWB + lcol;

    float x2a[4];   // rows mw*32 + (q>>1)*16 + (q&1)*8 + g
    {
        const float* x2s = (const float*)(sm + OFF_X2S);
        #pragma unroll
        for (int q = 0; q < 4; q++)
            x2a[q] = x2s[mw * 32 + (q >> 1) * 16 + (q & 1) * 8 + g];
    }

    float acc2[2][4] = {{0.f, 0.f, 0.f, 0.f}, {0.f, 0.f, 0.f, 0.f}};
    float acc[2][8][4];

    for (int t = 0; t < NTILES; t++) {
        // prefetch next M tile + y2 chunk into registers (hidden by mma)
        float mv[5];
        float y2v = 0.f;
        #pragma unroll
        for (int k = 0; k < 5; k++) {
            int i = k * THREADS + tid;              // < 1280 = 128*10
            int j = i / 10, c = i - j * 10;
            mv[k] = Mv[(size_t)(a_start + t * 128 + j) * NC + c];
        }
        if (tid < 128) y2v = g_y2[a_start + t * 128 + tid];
        #pragma unroll
        for (int mf = 0; mf < 2; mf++)
            #pragma unroll
            for (int nf = 0; nf < 8; nf++)
                #pragma unroll
                for (int q = 0; q < 4; q++) acc[mf][nf][q] = 0.f;

        CPWAIT1();              // Y buffer [t&1] ready
        __syncthreads();        // + prev GEMM-2 done reading W/Mt

        // ---- GEMM-1: 10 fp16 K-steps (K=16 each) ------------------------
        {
            const uint32_t yB = sb + OFF_Y0 + (t & 1) * SZ_YBUF;
            #pragma unroll
            for (int ks = 0; ks < 10; ks++) {
                uint32_t afr[2][4], bfr[4][4];
                #pragma unroll
                for (int mf = 0; mf < 2; mf++)
                    LDMX4(afr[mf], aA[mf] + ks * 32);
                #pragma unroll
                for (int p = 0; p < 4; p++)
                    LDMX4(bfr[p], yB + bBo[p] + ks * 32);
                #pragma unroll
                for (int mf = 0; mf < 2; mf++)
                    #pragma unroll
                    for (int p = 0; p < 4; p++) {
                        MMA_F16(acc[mf][p * 2],     afr[mf], bfr[p][0], bfr[p][2]);
                        MMA_F16(acc[mf][p * 2 + 1], afr[mf], bfr[p][1], bfr[p][3]);
                    }
            }
        }
        // publish Mt (bf16, transposed) + y2 chunk
        #pragma unroll
        for (int k = 0; k < 5; k++) {
            int i = k * THREADS + tid;
            int j = i / 10, c = i - j * 10;
            *(__nv_bfloat16*)(sm + OFF_MT + c * WROWB + j * 2) = __float2bfloat16(mv[k]);
        }
        if (tid < 128) ((float*)(sm + OFF_Y2S))[tid] = y2v;
        __syncthreads();        // Y buf consumed by all warps; Mt/y2 visible

        if (t + 2 < NTILES) issue_y(a_start + (t + 2) * 128, sb + OFF_Y0 + (t & 1) * SZ_YBUF, tid);
        CPCOMMIT();             // always one group per iter (may be empty)

        // ---- epilogue: d2 -> sqrt -> exp -> bf16 W tile ------------------
        {
            const float* y2s = (const float*)(sm + OFF_Y2S);
            float y2l[16];
            #pragma unroll
            for (int nf = 0; nf < 8; nf++) {
                y2l[nf * 2]     = y2s[nw * 64 + nf * 8 + tig * 2];
                y2l[nf * 2 + 1] = y2s[nw * 64 + nf * 8 + tig * 2 + 1];
            }
            #pragma unroll
            for (int mf = 0; mf < 2; mf++) {
                #pragma unroll
                for (int nf = 0; nf < 8; nf++) {
                    float w[4];
                    #pragma unroll
                    for (int q = 0; q < 4; q++) {
                        float d2 = fmaf(-2.f, acc[mf][nf][q],
                                        x2a[mf * 2 + (q >> 1)] + y2l[nf * 2 + (q & 1)]);
                        d2 = fmaxf(d2, 0.f);
                        float d;
                        asm("sqrt.approx.ftz.f32 %0, %1;" : "=f"(d) : "f"(d2));
                        asm("ex2.approx.ftz.f32 %0, %1;" : "=f"(w[q]) : "f"(d * KEXP));
                    }
                    __nv_bfloat162 p0 = __floats2bfloat162_rn(w[0], w[1]);
                    __nv_bfloat162 p1 = __floats2bfloat162_rn(w[2], w[3]);
                    int colb = (nw * 64 + nf * 8 + tig * 2) * 2;
                    int r0 = mw * 32 + mf * 16 + g;
                    *(__nv_bfloat162*)(sm + OFF_W + r0 * WROWB + colb) = p0;
                    *(__nv_bfloat162*)(sm + OFF_W + (r0 + 8) * WROWB + colb) = p1;
                }
            }
        }
        __syncthreads();        // W tile complete
        // ---- GEMM-2: acc2 += W[128x128] @ Mt^T[128x16] -------------------
        #pragma unroll
        for (int k2 = 0; k2 < 8; k2++) {
            uint32_t aw[4], bm[4];
            LDMX4(aw, aWb + k2 * 32);
            LDMX4(bm, bMb + k2 * 32);
            MMA_BF16(acc2[0], aw, bm[0], bm[2]);
            MMA_BF16(acc2[1], aw, bm[1], bm[3]);
        }
    }

    // --- write per-split partials: rows warp*16+g(+8), cols 2tig(+1) ----
    {
        int r0 = m_tile * 128 + warp * 16 + g;
        size_t base = ((size_t)split * NQ + r0) * 16 + tig * 2;
        #pragma unroll
        for (int nf = 0; nf < 2; nf++) {
            *(float2*)&g_part[base + nf * 8]          = make_float2(acc2[nf][0], acc2[nf][1]);
            *(float2*)&g_part[base + 8 * 16 + nf * 8] = make_float2(acc2[nf][2], acc2[nf][3]);
        }
    }
}

// ---------------------------------------------------------------------------
// Kernel 2: combine splits, normalize
// ---------------------------------------------------------------------------
__global__ void combine_kernel(float* __restrict__ out) {
    __shared__ float dsh[16];
    int tid = threadIdx.x;
    int il = tid >> 4, c = tid & 15;
    int i = blockIdx.x * 16 + il;
    float s = 0.f;
    #pragma unroll 4
    for (int sp = 0; sp < SPLITS; sp++)
        s += g_part[((size_t)sp * NQ + i) * 16 + c];
    if (c == 10) dsh[il] = s;
    __syncthreads();
    if (c < 10) out[(size_t)i * NC + c] = s / dsh[il];
}

// ---------------------------------------------------------------------------
// kernel_launch
// ---------------------------------------------------------------------------
extern "C" void kernel_launch(void* const* d_in, const int* in_sizes, int n_in,
                              void* d_out, int out_size) {
    const float* X  = (const float*)d_in[0];   // inputs  [4096, 160]
    const float* Y  = (const float*)d_in[1];   // Address [32768, 160]
    const float* Mv = (const float*)d_in[2];   // M       [32768, 10]
    float* out = (float*)d_out;                // [4096, 10]

    static bool attr_done = false;
    if (!attr_done) {
        cudaFuncSetAttribute(fused_kernel,
                             cudaFuncAttributeMaxDynamicSharedMemorySize, SMEM_BYTES);
        attr_done = true;
    }

    int norm_warps = NQ + NA;
    norms_kernel<<<(norm_warps * 32 + 255) / 256, 256>>>(X, Y);
    fused_kernel<<<(NQ / 128) * SPLITS, THREADS, SMEM_BYTES>>>(Mv);
    combine_kernel<<<NQ / 16, 256>>>(out);
}

// round 5
// speedup vs baseline: 1.7734x; 1.2510x over previous
#include <cuda_runtime.h>
#include <cuda_fp16.h>
#include <cstdint>

// ---------------------------------------------------------------------------
// Problem constants
// ---------------------------------------------------------------------------
#define THREADS 256
#define F_DIM 160
#define NQ 4096
#define NA 32768
#define NC 10
#define SPLITS 32
#define A_CHUNK 1024          // addresses per CTA
#define TN 64                 // N tile (addresses per tile)
#define NTILES (A_CHUNK / TN) // 16
#define KEXP (-1.31154095f)   // -log2(e)/1.1 : exp(-d/1.1) = 2^(d*KEXP)
#define WSHIFT 24.0f          // per-problem weight scale 2^24 (softmin-invariant)
#define TCLAMP 14.0f          // clamp t -> w <= 2^14 (fp16-safe)

// ---------------------------------------------------------------------------
// Shared memory layout (fp16 tiles, 336B row stride: 84*r mod 32 distinct
// bank quads for 8-row ldmatrix groups -> conflict-free; 144B likewise)
// ---------------------------------------------------------------------------
#define ROWB 336
#define WROWB 144                      // 72 fp16 (64 used)
#define MTROWB 144
#define OFF_X   0
#define SZ_X    (128 * ROWB)           // 43008
#define OFF_Y0  SZ_X                   // 43008
#define SZ_YBUF (TN * ROWB)            // 21504
#define OFF_Y1  (OFF_Y0 + SZ_YBUF)     // 64512
#define OFF_W   (OFF_Y1 + SZ_YBUF)     // 86016
#define SZ_W    (128 * WROWB)          // 18432
#define OFF_MT  (OFF_W + SZ_W)         // 104448  Mt[16][72] fp16 (M^T + ones)
#define SZ_MT   (16 * MTROWB)          // 2304
#define OFF_Y2S (OFF_MT + SZ_MT)       // 106752  y2 chunk [64] f32
#define OFF_X2S (OFF_Y2S + 256)        // 107008  x2 tile [128] f32
#define SMEM_BYTES (OFF_X2S + 512)     // 107520  (x2 -> 2 CTAs/SM)

// ---------------------------------------------------------------------------
// Device scratch
// ---------------------------------------------------------------------------
__device__ __half g_xh[(size_t)NQ * F_DIM];
__device__ __half g_yh[(size_t)NA * F_DIM];
__device__ float g_x2[NQ];
__device__ float g_y2[NA];
__device__ float g_part[(size_t)SPLITS * NQ * 16];  // [split][row][16]: 10 num, den@10

// ---------------------------------------------------------------------------
// PTX helpers
// ---------------------------------------------------------------------------
__device__ __forceinline__ uint32_t cvta_s(const void* p) {
    uint32_t r;
    asm("{ .reg .u64 t; cvta.to.shared.u64 t, %1; cvt.u32.u64 %0, t; }"
        : "=r"(r) : "l"(p));
    return r;
}

#define LDMX4(r, a)                                                            \
    asm volatile("ldmatrix.sync.aligned.m8n8.x4.shared.b16 {%0,%1,%2,%3}, [%4];" \
                 : "=r"((r)[0]), "=r"((r)[1]), "=r"((r)[2]), "=r"((r)[3])      \
                 : "r"(a))

#define MMA_F16(d, a, b0, b1)                                                  \
    asm volatile("mma.sync.aligned.m16n8k16.row.col.f32.f16.f16.f32 "          \
                 "{%0,%1,%2,%3},{%4,%5,%6,%7},{%8,%9},{%0,%1,%2,%3};"          \
                 : "+f"((d)[0]), "+f"((d)[1]), "+f"((d)[2]), "+f"((d)[3])      \
                 : "r"((a)[0]), "r"((a)[1]), "r"((a)[2]), "r"((a)[3]),         \
                   "r"(b0), "r"(b1))

#define CPASYNC16(d, s)                                                        \
    asm volatile("cp.async.cg.shared.global [%0], [%1], 16;" :: "r"(d), "l"(s))
#define CPCOMMIT() asm volatile("cp.async.commit_group;" ::: "memory")
#define CPWAIT1()  asm volatile("cp.async.wait_group 1;" ::: "memory")

// issue cp.async for one Y tile (fp16): rows [a0row, a0row+64), 320B/row
__device__ __forceinline__ void issue_y(int a0row, uint32_t dbase, int tid) {
    const char* gs = (const char*)(g_yh + (size_t)a0row * F_DIM);
    #pragma unroll
    for (int k = 0; k < 5; k++) {
        int i = k * THREADS + tid;        // 64 rows x 20 x 16B
        int r = i / 20, c = i - r * 20;
        CPASYNC16(dbase + r * ROWB + c * 16, gs + (size_t)r * 320 + c * 16);
    }
}

// ---------------------------------------------------------------------------
// Kernel 0: exact fp32 row norms + fp16 conversion (vectorized)
// ---------------------------------------------------------------------------
__global__ void norms_kernel(const float* __restrict__ X, const float* __restrict__ Y) {
    int gw = (int)((blockIdx.x * blockDim.x + threadIdx.x) >> 5);
    int lane = threadIdx.x & 31;
    const float4* src;
    uint2* dsth;
    float* dst;
    if (gw < NQ) {
        src = (const float4*)(X + (size_t)gw * F_DIM);
        dsth = (uint2*)(g_xh + (size_t)gw * F_DIM); dst = g_x2 + gw;
    } else if (gw < NQ + NA) {
        int r = gw - NQ;
        src = (const float4*)(Y + (size_t)r * F_DIM);
        dsth = (uint2*)(g_yh + (size_t)r * F_DIM); dst = g_y2 + r;
    } else return;
    float s = 0.f;
    #pragma unroll
    for (int k = 0; k < 2; k++) {
        int j = lane + k * 32;
        if (k == 0 || j < 40) {
            float4 v = src[j];
            s = fmaf(v.x, v.x, s); s = fmaf(v.y, v.y, s);
            s = fmaf(v.z, v.z, s); s = fmaf(v.w, v.w, s);
            __half2 h0 = __floats2half2_rn(v.x, v.y);
            __half2 h1 = __floats2half2_rn(v.z, v.w);
            uint2 u;
            u.x = *(uint32_t*)&h0; u.y = *(uint32_t*)&h1;
            dsth[j] = u;
        }
    }
    #pragma unroll
    for (int o = 16; o > 0; o >>= 1) s += __shfl_xor_sync(0xFFFFFFFFu, s, o);
    if (lane == 0) *dst = s;
}

// ---------------------------------------------------------------------------
// Kernel 1: fused scores(fp16 mma) -> shifted softmin weights (fp16) -> W@[M|1]
// grid = 32 m-tiles x 32 A-splits; 256 threads; 2 CTAs/SM (phase overlap)
// GEMM-1 warp grid 4(m) x 2(n); warp tile 32x32
// ---------------------------------------------------------------------------
__global__ void __launch_bounds__(THREADS, 2) fused_kernel(
    const float* __restrict__ Mv)
{
    extern __shared__ __align__(1024) char sm[];
    const uint32_t sb = cvta_s(sm);
    const int tid  = threadIdx.x;
    const int lane = tid & 31, warp = tid >> 5;
    const int mw = warp >> 1, nw = warp & 1;
    const int g = lane >> 2, tig = lane & 3;
    const int m_tile = (int)blockIdx.x >> 5;
    const int split  = (int)blockIdx.x & (SPLITS - 1);
    const int a_start = split * A_CHUNK;

    // --- prologue: async-load Y tiles 0 and 1 ---------------------------
    issue_y(a_start, sb + OFF_Y0, tid); CPCOMMIT();
    issue_y(a_start + TN, sb + OFF_Y1, tid); CPCOMMIT();

    // --- X tile (fp16, once per CTA), x2 chunk, constant Mt rows --------
    {
        const char* xg = (const char*)(g_xh + (size_t)m_tile * 128 * F_DIM);
        #pragma unroll
        for (int k = 0; k < 10; k++) {
            int i = k * THREADS + tid;
            int r = i / 20, c = i - r * 20;
            *(uint4*)(sm + OFF_X + r * ROWB + c * 16) =
                *(const uint4*)(xg + (size_t)r * 320 + c * 16);
        }
    }
    if (tid < 128) ((float*)(sm + OFF_X2S))[tid] = g_x2[m_tile * 128 + tid];
    {   // Mt rows 10..15: ones column (den), zeros elsewhere (written once)
        __half one = __float2half(1.0f);
        __half zro = __float2half(0.0f);
        for (int i = tid; i < 6 * TN; i += THREADS) {
            int c = 10 + i / TN, j = i - (c - 10) * TN;
            *(__half*)(sm + OFF_MT + c * MTROWB + j * 2) = (c == 10) ? one : zro;
        }
    }
    __syncthreads();

    // --- per-thread ldmatrix bases --------------------------------------
    const int lrow = (lane & 7) + ((lane >> 3) & 1) * 8;
    const int lcol = ((lane >> 4) & 1) * 16;      // k 0-7 | 8-15 byte offset
    uint32_t aA[2];
    #pragma unroll
    for (int mf = 0; mf < 2; mf++)
        aA[mf] = sb + OFF_X + (mw * 32 + mf * 16 + lrow) * ROWB + lcol;
    uint32_t bBo[2];
    #pragma unroll
    for (int p = 0; p < 2; p++)
        bBo[p] = (uint32_t)((nw * 32 + p * 16 + lrow) * ROWB + lcol);
    const uint32_t aWb = sb + OFF_W + (warp * 16 + lrow) * WROWB + lcol;
    const uint32_t bMb = sb + OFF_MT + lrow * MTROWB + lcol;

    float x2a[4];   // rows mw*32 + mf*16 + (q>>1)*8 + g
    {
        const float* x2s = (const float*)(sm + OFF_X2S);
        #pragma unroll
        for (int q = 0; q < 4; q++)
            x2a[q] = x2s[mw * 32 + (q >> 1) * 16 + (q & 1) * 8 + g];
    }

    float acc2[2][4] = {{0.f, 0.f, 0.f, 0.f}, {0.f, 0.f, 0.f, 0.f}};
    float acc[2][4][4];

    for (int t = 0; t < NTILES; t++) {
        // prefetch next M tile (64x10) + y2 chunk into registers
        float mv[3];
        float y2v = 0.f;
        #pragma unroll
        for (int k = 0; k < 3; k++) {
            int i = k * THREADS + tid;
            if (i < TN * NC) {
                int j = i / 10, c = i - j * 10;
                mv[k] = Mv[(size_t)(a_start + t * TN + j) * NC + c];
            }
        }
        if (tid < TN) y2v = g_y2[a_start + t * TN + tid];
        #pragma unroll
        for (int mf = 0; mf < 2; mf++)
            #pragma unroll
            for (int nf = 0; nf < 4; nf++)
                #pragma unroll
                for (int q = 0; q < 4; q++) acc[mf][nf][q] = 0.f;

        CPWAIT1();              // Y buffer [t&1] ready
        __syncthreads();        // + prev GEMM-2 done reading W/Mt

        // ---- GEMM-1: 10 fp16 K-steps (K=16 each), 8 MMA per step --------
        {
            const uint32_t yB = sb + OFF_Y0 + (t & 1) * SZ_YBUF;
            #pragma unroll
            for (int ks = 0; ks < 10; ks++) {
                uint32_t afr[2][4], bfr[2][4];
                #pragma unroll
                for (int mf = 0; mf < 2; mf++)
                    LDMX4(afr[mf], aA[mf] + ks * 32);
                #pragma unroll
                for (int p = 0; p < 2; p++)
                    LDMX4(bfr[p], yB + bBo[p] + ks * 32);
                #pragma unroll
                for (int mf = 0; mf < 2; mf++)
                    #pragma unroll
                    for (int p = 0; p < 2; p++) {
                        MMA_F16(acc[mf][p * 2],     afr[mf], bfr[p][0], bfr[p][2]);
                        MMA_F16(acc[mf][p * 2 + 1], afr[mf], bfr[p][1], bfr[p][3]);
                    }
            }
        }
        // publish Mt (fp16, transposed) + y2 chunk
        #pragma unroll
        for (int k = 0; k < 3; k++) {
            int i = k * THREADS + tid;
            if (i < TN * NC) {
                int j = i / 10, c = i - j * 10;
                *(__half*)(sm + OFF_MT + c * MTROWB + j * 2) = __float2half_rn(mv[k]);
            }
        }
        if (tid < TN) ((float*)(sm + OFF_Y2S))[tid] = y2v;
        __syncthreads();        // Y buf consumed; Mt/y2 visible

        if (t + 2 < NTILES) issue_y(a_start + (t + 2) * TN, sb + OFF_Y0 + (t & 1) * SZ_YBUF, tid);
        CPCOMMIT();

        // ---- epilogue: d2 -> sqrt -> t=KEXP*d+S -> ex2.f16x2 -> W fp16 ---
        {
            const float* y2s = (const float*)(sm + OFF_Y2S);
            float y2l[8];
            #pragma unroll
            for (int nf = 0; nf < 4; nf++) {
                y2l[nf * 2]     = y2s[nw * 32 + nf * 8 + tig * 2];
                y2l[nf * 2 + 1] = y2s[nw * 32 + nf * 8 + tig * 2 + 1];
            }
            #pragma unroll
            for (int mf = 0; mf < 2; mf++) {
                #pragma unroll
                for (int nf = 0; nf < 4; nf++) {
                    float tt[4];
                    #pragma unroll
                    for (int q = 0; q < 4; q++) {
                        float d2 = fmaf(-2.f, acc[mf][nf][q],
                                        x2a[mf * 2 + (q >> 1)] + y2l[nf * 2 + (q & 1)]);
                        d2 = fmaxf(d2, 0.f);
                        float d;
                        asm("sqrt.approx.ftz.f32 %0, %1;" : "=f"(d) : "f"(d2));
                        tt[q] = fminf(fmaf(KEXP, d, WSHIFT), TCLAMP);
                    }
                    __half2 t0 = __floats2half2_rn(tt[0], tt[1]);
                    __half2 t1 = __floats2half2_rn(tt[2], tt[3]);
                    uint32_t w0, w1;
                    asm("ex2.approx.f16x2 %0, %1;" : "=r"(w0) : "r"(*(uint32_t*)&t0));
                    asm("ex2.approx.f16x2 %0, %1;" : "=r"(w1) : "r"(*(uint32_t*)&t1));
                    int colb = (nw * 32 + nf * 8 + tig * 2) * 2;
                    int r0 = mw * 32 + mf * 16 + g;
                    *(uint32_t*)(sm + OFF_W + r0 * WROWB + colb) = w0;
                    *(uint32_t*)(sm + OFF_W + (r0 + 8) * WROWB + colb) = w1;
                }
            }
        }
        __syncthreads();        // W tile complete
        // ---- GEMM-2: acc2 += W[128x64] @ Mt^T[64x16] ---------------------
        #pragma unroll
        for (int k2 = 0; k2 < 4; k2++) {
            uint32_t aw[4], bm[4];
            LDMX4(aw, aWb + k2 * 32);
            LDMX4(bm, bMb + k2 * 32);
            MMA_F16(acc2[0], aw, bm[0], bm[2]);
            MMA_F16(acc2[1], aw, bm[1], bm[3]);
        }
    }

    // --- write per-split partials ---------------------------------------
    {
        int r0 = m_tile * 128 + warp * 16 + g;
        size_t base = ((size_t)split * NQ + r0) * 16 + tig * 2;
        #pragma unroll
        for (int nf = 0; nf < 2; nf++) {
            *(float2*)&g_part[base + nf * 8]          = make_float2(acc2[nf][0], acc2[nf][1]);
            *(float2*)&g_part[base + 8 * 16 + nf * 8] = make_float2(acc2[nf][2], acc2[nf][3]);
        }
    }
}

// ---------------------------------------------------------------------------
// Kernel 2: combine splits, normalize
// ---------------------------------------------------------------------------
__global__ void combine_kernel(float* __restrict__ out) {
    __shared__ float dsh[16];
    int tid = threadIdx.x;
    int il = tid >> 4, c = tid & 15;
    int i = blockIdx.x * 16 + il;
    float s = 0.f;
    #pragma unroll 4
    for (int sp = 0; sp < SPLITS; sp++)
        s += g_part[((size_t)sp * NQ + i) * 16 + c];
    if (c == 10) dsh[il] = s;
    __syncthreads();
    if (c < 10) out[(size_t)i * NC + c] = s / dsh[il];
}

// ---------------------------------------------------------------------------
// kernel_launch
// ---------------------------------------------------------------------------
extern "C" void kernel_launch(void* const* d_in, const int* in_sizes, int n_in,
                              void* d_out, int out_size) {
    const float* X  = (const float*)d_in[0];   // inputs  [4096, 160]
    const float* Y  = (const float*)d_in[1];   // Address [32768, 160]
    const float* Mv = (const float*)d_in[2];   // M       [32768, 10]
    float* out = (float*)d_out;                // [4096, 10]

    static bool attr_done = false;
    if (!attr_done) {
        cudaFuncSetAttribute(fused_kernel,
                             cudaFuncAttributeMaxDynamicSharedMemorySize, SMEM_BYTES);
        attr_done = true;
    }

    int norm_warps = NQ + NA;
    norms_kernel<<<(norm_warps * 32 + 255) / 256, 256>>>(X, Y);
    fused_kernel<<<(NQ / 128) * SPLITS, THREADS, SMEM_BYTES>>>(Mv);
    combine_kernel<<<NQ / 16, 256>>>(out);
}